// round 17
// baseline (speedup 1.0000x reference)
#include <cuda_runtime.h>
#include <math_constants.h>

// CropProposals: 3D ROI 2x2x2 adaptive max-pool.
// fm:      (4, 64, 24, 24, 24) f32   -> d_in[0]
// corners: (4, 64, 2, 3)       f32   -> d_in[1]
// out:     (4, 64, 64, 2, 2, 2) f32
//
// z-VECTORIZED lane mapping: z-union padded to even start (zs = zlo & ~1),
// W2 = ceil(width/2) z-PAIRS; lane -> (hrel = lane/W2, pair zrel2 = lane%W2).
// One LDG.64 loads 2 z-voxels -> a step covers R = 32/W2 h-rows x full union.
// Per axis both bins have EQUAL length m2=(n+1)/2 at lo and lo+n/2 (shared
// middle, max-idempotent). No predication: out-of-range lanes clamp onto
// in-bin duplicates; out-of-union z elements are masked per-element in the
// kz epilogue. Each warp: 2 channels (immediate-offset LDGs). 2 warps per
// task split d by parity; block = 8 warps = 4 cslots x 2 halves, one (b,p).
// z-binning via redux.sync on order-preserving keys; halves combined in smem.

#define NEGINF (-CUDART_INF_F)
#define KEY_NEGINF 0x007FFFFFu   // f2key(-inf)
#define CH_STRIDE 13824          // floats per channel volume

__device__ __forceinline__ unsigned f2key(float f) {
    int i = __float_as_int(f);
    return (unsigned)(i ^ ((i >> 31) | 0x80000000));
}
__device__ __forceinline__ float key2f(unsigned u) {
    int i = (int)(u ^ ((~u >> 31) ? 0xFFFFFFFFu : 0x80000000u));
    return __int_as_float(i);
}
__device__ __forceinline__ void fmax2(float2& a, float2 v) {
    a.x = fmaxf(a.x, v.x);
    a.y = fmaxf(a.y, v.y);
}

__global__ __launch_bounds__(256) void crop_proposals_kernel(
    const float* __restrict__ fm,
    const float* __restrict__ corners,
    float* __restrict__ out)
{
    __shared__ unsigned skey[8][16];      // [warp][ch*8 + slot]

    const int lane  = threadIdx.x & 31;
    const int wid   = threadIdx.x >> 5;   // 0..7
    const int cslot = wid >> 1;           // 0..3 : channel slot (2 ch each)
    const int half  = wid & 1;            // 0/1  : d-parity split

    const int bp = blockIdx.x >> 3;       // b*64 + p
    const int cg = blockIdx.x & 7;        // channel group (8 channels each)
    const int b  = bp >> 6;
    const int c0 = cg * 8 + cslot * 2;    // first of this warp's 2 channels

    // ---- bin computation (matches JAX _pool_masks exactly, fp32) ----
    const float* cor = corners + bp * 6;
    int blo[3], nn[3];
#pragma unroll
    for (int a = 0; a < 3; a++) {
        float ll = __ldg(cor + a)     * 0.25f;
        float ur = __ldg(cor + 3 + a) * 0.25f;
        ll = fminf(fmaxf(ll, 0.0f), 21.0f);
        ur = (ur - ll >= 2.0f) ? ur : (ll + 2.0f);
        ur = fminf(fmaxf(ur, 2.0f), 23.0f);
        int lo = (int)floorf(ll);
        blo[a] = lo;
        nn[a]  = (int)floorf(ur) - lo;   // n in [2, 23]
    }
    // equal-length bins: [lo, lo+m2) and [lo+n/2, lo+n/2+m2), m2 = (n+1)/2
    const int d0   = blo[0], md2 = (nn[0] + 1) >> 1, ddel = (nn[0] >> 1) * 576;
    const int h0   = blo[1], mh2 = (nn[1] + 1) >> 1, hseg = (nn[1] >> 1) * 24;
    const int zlo  = blo[2], mz2 = (nn[2] + 1) >> 1, zhalf = nn[2] >> 1;
    const int zhi  = zlo + nn[2];        // exclusive union end

    // ---- z-pair lane mapping ----
    const int zs    = zlo & ~1;               // even-aligned pair start
    const int W2    = (zhi - zs + 1) >> 1;    // z-pairs covering the union
    const int R     = 32 / W2;                // h-rows per load step
    const int hrel  = lane / W2;
    const int zrel2 = lane - hrel * W2;
    const int z0    = min(zs + 2 * zrel2, 22);  // pair (z0, z0+1), stays <= 23
    const int hcap  = mh2 - 1;                // h clamp target (inside bin)

    const float* base = fm + ((size_t)(b * 64 + c0)) * CH_STRIDE + z0;

    float2 acc[2][4];                    // [ch][kx*2+ky], .x=z0 .y=z0+1
#pragma unroll
    for (int ch = 0; ch < 2; ch++)
#pragma unroll
        for (int q = 0; q < 4; q++)
            acc[ch][q] = make_float2(NEGINF, NEGINF);

    // ---- main loop: this warp takes d index i = half, half+2, ... < md2 ----
    for (int i = half; i < md2; i += 2) {
        const float* pA = base + (d0 + i) * 576;   // kx0 stream
        const float* pC = pA + ddel;               // kx1 stream
        for (int idx0 = 0; idx0 < mh2; idx0 += R) {
            const int ro = (h0 + min(idx0 + hrel, hcap)) * 24;
            const float* qA0 = pA + ro;
            const float* qA1 = pA + ro + hseg;
            const float* qC0 = pC + ro;
            const float* qC1 = pC + ro + hseg;
#pragma unroll
            for (int ch = 0; ch < 2; ch++) {      // immediate offsets ch*CH_STRIDE
                fmax2(acc[ch][0], __ldg((const float2*)(qA0 + ch * CH_STRIDE)));
                fmax2(acc[ch][1], __ldg((const float2*)(qA1 + ch * CH_STRIDE)));
                fmax2(acc[ch][2], __ldg((const float2*)(qC0 + ch * CH_STRIDE)));
                fmax2(acc[ch][3], __ldg((const float2*)(qC1 + ch * CH_STRIDE)));
            }
        }
    }

    // ---- per-warp kz reductions: per-element z masks + redux on keys ----
#pragma unroll
    for (int kz = 0; kz < 2; kz++) {
        const int zb = zlo + (kz ? zhalf : 0);        // bin [zb, zb + mz2)
        const bool in0 = (unsigned)(z0     - zb) < (unsigned)mz2;
        const bool in1 = (unsigned)(z0 + 1 - zb) < (unsigned)mz2;
#pragma unroll
        for (int ch = 0; ch < 2; ch++) {
#pragma unroll
            for (int q = 0; q < 4; q++) {     // q = kx*2 + ky
                const float t = fmaxf(in0 ? acc[ch][q].x : NEGINF,
                                      in1 ? acc[ch][q].y : NEGINF);
                unsigned mv = __reduce_max_sync(0xFFFFFFFFu, f2key(t));
                if (lane == 0)
                    skey[wid][ch * 8 + q * 2 + kz] = mv;
            }
        }
    }
    __syncthreads();

    // ---- combine halves + write: threads 0..63, one output value each ----
    const int tid = threadIdx.x;
    if (tid < 64) {
        const int ocs = tid >> 4;          // channel slot 0..3
        const int ch  = (tid >> 3) & 1;    // channel within slot
        const int k   = tid & 7;           // output slot kx*4+ky*2+kz
        const int s   = ch * 8 + k;
        unsigned v = max(skey[ocs * 2 + 0][s], skey[ocs * 2 + 1][s]);
        const int oc = cg * 8 + ocs * 2 + ch;
        out[(((size_t)bp * 64 + oc) << 3) + k] = key2f(v);
    }
}

extern "C" void kernel_launch(void* const* d_in, const int* in_sizes, int n_in,
                              void* d_out, int out_size)
{
    const float* fm      = (const float*)d_in[0];
    const float* corners = (const float*)d_in[1];
    float* out           = (float*)d_out;

    // 256 (b,p) x 8 channel-groups = 2048 blocks, 8 warps each
    crop_proposals_kernel<<<2048, 256>>>(fm, corners, out);
}